// round 12
// baseline (speedup 1.0000x reference)
#include <cuda_runtime.h>
#include <cuda_bf16.h>
#include <math.h>

#define NT     256
#define VOCAB  256
#define EMPTYE (-(1 << 28))   // exponent sentinel for "group has no mass"

// per-batch partial losses (loss_b / tl_b)
__device__ float g_partial[1024];

// 2^d for d <= 0 (flushes to 0 below -126). d==0 -> 1.0f.
__device__ __forceinline__ float exp2i_neg(int d) {
    return (d < -126) ? 0.f : __int_as_float((127 + d) << 23);
}

// Constant-index float4 component access (folds under full unroll).
__device__ __forceinline__ float f4c(float4 v, int c) {
    switch (c & 3) {
        case 0:  return v.x;
        case 1:  return v.y;
        case 2:  return v.z;
        default: return v.w;
    }
}

__device__ __forceinline__ float4 shfl_up_f4(float4 v, unsigned d) {
    float4 r;
    r.x = __shfl_up_sync(0xffffffffu, v.x, d);
    r.y = __shfl_up_sync(0xffffffffu, v.y, d);
    r.z = __shfl_up_sync(0xffffffffu, v.z, d);
    r.w = __shfl_up_sync(0xffffffffu, v.w, d);
    return r;
}

// One CTA per batch element. Linear-domain CTC forward scan,
// per-group (4-state) block-floating-point exponents,
// EIGHT time steps fused per barrier (16-state halo pyramid, in registers),
// time-transposed probability staging, and SHUFFLE-SHARED label prob vectors:
// each thread loads only its own 2 labels; the 11 halo vectors come from
// neighboring lanes via __shfl_up (LDS fallback for lanes < distance).
__global__ __launch_bounds__(NT, 1) void ctc_scan(
    const float* __restrict__ logp,      // [B, T, VOCAB]
    const int*   __restrict__ targets,   // [B, S]
    const int*   __restrict__ input_len, // [B]
    const int*   __restrict__ target_len,// [B]
    int T, int S)
{
    const int b   = blockIdx.x;
    const int tid = threadIdx.x;
    const int lane = tid & 31;
    const float* lp = logp    + (size_t)b * T * VOCAB;
    const int*   tg = targets + (size_t)b * S;
    const int il = input_len[b];
    const int tl = target_len[b];
    const int Lb = 2 * tl + 1;               // number of valid extended states
    const int ng = (Lb + 3) >> 2;            // groups of 4 states

    // alpha mantissas at abuf[buf][16 + s]; [0..15] zero padding for the halo.
    __shared__ float  abuf[2][824];
    __shared__ int    gexp[2][204];          // per-group exponents
    __shared__ float4 pshA[2][VOCAB];        // [buf][v] = exp(logp[t..t+3][v])
    __shared__ float4 pshB[2][VOCAB];        // [buf][v] = exp(logp[t+4..t+7][v])

    for (int j = tid; j < 824; j += NT) { abuf[0][j] = 0.f; abuf[1][j] = 0.f; }
    for (int j = tid; j < 204; j += NT) { gexp[0][j] = EMPTYE; gexp[1][j] = EMPTYE; }
    __syncthreads();

    // Thread i owns states 4i..4i+3; pyramid spans states 4i-16..4i+3 (k=0..19).
    // Odd k=2m+1 -> state 4i-16+k has label tg[2i-8+m], m=0..9.
    const int i = tid;
    int   lbl[10];
    float csv[10];
    float m0 = 0.f, m1 = 0.f, m2 = 0.f, m3 = 0.f;
    const bool isg = (i < ng);
    #pragma unroll
    for (int m = 0; m < 10; ++m) { lbl[m] = 0; csv[m] = 0.f; }
    {
        #pragma unroll
        for (int m = 0; m < 10; ++m) {
            int j = 2 * i - 8 + m;
            int lj  = (j >= 0 && j < S) ? tg[j] : 0;
            int ljm = (j - 1 >= 0 && j - 1 < S) ? tg[j - 1] : -1;
            lbl[m] = lj;
            csv[m] = (j >= 1 && lj != ljm) ? 1.f : 0.f;
        }
        int s0 = 4 * i;
        m0 = (isg && s0     < Lb) ? 1.f : 0.f;
        m1 = (isg && s0 + 1 < Lb) ? 1.f : 0.f;
        m2 = (isg && s0 + 2 < Lb) ? 1.f : 0.f;
        m3 = (isg && s0 + 3 < Lb) ? 1.f : 0.f;
    }

    #define RAW(r) (((r) < T) ? lp[(size_t)(r) * VOCAB + tid] : 0.f)
    #define EXPG(r) (((r) < T) ? __expf(lp[(size_t)(r) * VOCAB + tid]) : 0.f)
    // Prologue: stage exp rows 1..8; raw queue q0..q7 = rows 9..16.
    pshA[0][tid] = make_float4(EXPG(1), EXPG(2), EXPG(3), EXPG(4));
    pshB[0][tid] = make_float4(EXPG(5), EXPG(6), EXPG(7), EXPG(8));
    float q0 = RAW(9),  q1 = RAW(10), q2 = RAW(11), q3 = RAW(12);
    float q4 = RAW(13), q5 = RAW(14), q6 = RAW(15), q7 = RAW(16);
    // alpha_0: states 0 (blank) and 1 (first target); group 0 exponent = 0.
    if (tid == 0) { abuf[0][16] = __expf(lp[1]); gexp[0][0] = 0; }
    if (tid == 1) { abuf[0][17] = __expf(lp[tg[0]]); }
    __syncthreads();

    int cur = 0, pb = 0;
    int t = 1;

    // Fused loop: each iteration advances steps t..t+7 with ONE barrier.
    for (; t + 7 < il; t += 8) {
        // Stage exp rows t+8..t+15; refill queue with rows t+16..t+23.
        pshA[pb ^ 1][tid] = make_float4(__expf(q0), __expf(q1), __expf(q2), __expf(q3));
        pshB[pb ^ 1][tid] = make_float4(__expf(q4), __expf(q5), __expf(q6), __expf(q7));
        q0 = RAW(t + 16); q1 = RAW(t + 17); q2 = RAW(t + 18); q3 = RAW(t + 19);
        q4 = RAW(t + 20); q5 = RAW(t + 21); q6 = RAW(t + 22); q7 = RAW(t + 23);

        // ---- Label prob vectors: own loads + shuffle-shared halo (no divergence) ----
        const float4* PA = pshA[pb];
        const float4* PB = pshB[pb];
        float4 BKlo = PA[1];
        float4 BKhi = PB[1];
        float4 Plo[10], Phi[10];
        // own labels m=8 (tg[2i]) and m=9 (tg[2i+1])
        Plo[8] = PA[lbl[8]];  Plo[9] = PA[lbl[9]];
        Phi[8] = PB[lbl[8]];  Phi[9] = PB[lbl[9]];
        // halo: thread i-d's own vectors are this thread's m = 8-2d, 9-2d
        Plo[0] = shfl_up_f4(Plo[8], 4);  Plo[1] = shfl_up_f4(Plo[9], 4);
        Plo[2] = shfl_up_f4(Plo[8], 3);  Plo[3] = shfl_up_f4(Plo[9], 3);
        Plo[4] = shfl_up_f4(Plo[8], 2);  Plo[5] = shfl_up_f4(Plo[9], 2);
        Plo[6] = shfl_up_f4(Plo[8], 1);  Plo[7] = shfl_up_f4(Plo[9], 1);
        Phi[5] = shfl_up_f4(Phi[9], 2);
        Phi[6] = shfl_up_f4(Phi[8], 1);  Phi[7] = shfl_up_f4(Phi[9], 1);
        // cross-warp boundary lanes: fall back to direct gathers
        if (lane < 4) { Plo[0] = PA[lbl[0]]; Plo[1] = PA[lbl[1]]; }
        if (lane < 3) { Plo[2] = PA[lbl[2]]; Plo[3] = PA[lbl[3]]; }
        if (lane < 2) { Plo[4] = PA[lbl[4]]; Plo[5] = PA[lbl[5]]; Phi[5] = PB[lbl[5]]; }
        if (lane < 1) { Plo[6] = PA[lbl[6]]; Plo[7] = PA[lbl[7]];
                        Phi[6] = PB[lbl[6]]; Phi[7] = PB[lbl[7]]; }

        // Own states reachable at step t+7 iff 4i <= 2(t+7)+1.
        if (isg && 4 * i <= 2 * t + 15) {
            const float* A = abuf[cur];
            float4 g0 = *(const float4*)(A +      4 * i);   // k 0..3   (states 4i-16..)
            float4 g1 = *(const float4*)(A +  4 + 4 * i);   // k 4..7
            float4 g2 = *(const float4*)(A +  8 + 4 * i);   // k 8..11
            float4 g3 = *(const float4*)(A + 12 + 4 * i);   // k 12..15
            float4 g4 = *(const float4*)(A + 16 + 4 * i);   // k 16..19 (own)
            int E0 = (i > 3) ? gexp[cur][i - 4] : EMPTYE;
            int E1 = (i > 2) ? gexp[cur][i - 3] : EMPTYE;
            int E2 = (i > 1) ? gexp[cur][i - 2] : EMPTYE;
            int E3 = (i > 0) ? gexp[cur][i - 1] : EMPTYE;
            int E4 = gexp[cur][i];
            int Eref = max(max(max(E0, E1), max(E2, E3)), E4);
            float s0 = exp2i_neg(E0 - Eref);
            float s1 = exp2i_neg(E1 - Eref);
            float s2 = exp2i_neg(E2 - Eref);
            float s3 = exp2i_neg(E3 - Eref);
            float s4 = exp2i_neg(E4 - Eref);

            float xs[20];
            xs[0]=g0.x*s0;  xs[1]=g0.y*s0;  xs[2]=g0.z*s0;  xs[3]=g0.w*s0;
            xs[4]=g1.x*s1;  xs[5]=g1.y*s1;  xs[6]=g1.z*s1;  xs[7]=g1.w*s1;
            xs[8]=g2.x*s2;  xs[9]=g2.y*s2;  xs[10]=g2.z*s2; xs[11]=g2.w*s2;
            xs[12]=g3.x*s3; xs[13]=g3.y*s3; xs[14]=g3.z*s3; xs[15]=g3.w*s3;
            xs[16]=g4.x*s4; xs[17]=g4.y*s4; xs[18]=g4.z*s4; xs[19]=g4.w*s4;

            // 8 layers; layer j computes k = 2j..19 in DESCENDING k (in-place).
            #pragma unroll
            for (int j = 1; j <= 8; ++j) {
                float pbj = (j <= 4) ? f4c(BKlo, j - 1) : f4c(BKhi, j - 5);
                #pragma unroll
                for (int k = 19; k >= 2 * j; --k) {
                    if ((k & 1) == 0) {
                        xs[k] = (xs[k] + xs[k - 1]) * pbj;
                    } else {
                        const int m = (k - 1) >> 1;
                        float pl = (j <= 4) ? f4c(Plo[m], j - 1) : f4c(Phi[m], j - 5);
                        xs[k] = (xs[k] + xs[k - 1] + csv[m] * xs[k - 2]) * pl;
                    }
                }
            }

            // Mask own 4 outputs, renormalize group, store.
            float n0 = xs[16] * m0, n1 = xs[17] * m1, n2 = xs[18] * m2, n3 = xs[19] * m3;
            float gm = fmaxf(fmaxf(n0, n1), fmaxf(n2, n3));
            int newE; float sc;
            if (gm > 0.f) {
                int e = ((__float_as_int(gm) >> 23) & 255) - 127;
                newE = Eref + e;
                sc = __int_as_float((127 - e) << 23);   // 2^-e
            } else {
                newE = EMPTYE;
                sc = 0.f;
            }
            *(float4*)(abuf[cur ^ 1] + 16 + 4 * i) =
                make_float4(n0 * sc, n1 * sc, n2 * sc, n3 * sc);
            gexp[cur ^ 1][i] = newE;
        }

        __syncthreads();
        cur ^= 1;
        pb ^= 1;
    }

    // Single-step tail (up to 7 steps). Row t+st: component st of pshA (st<4)
    // or component st-4 of pshB.
    int st = 0;
    for (; t < il; ++t, ++st) {
        if (isg && 4 * i <= 2 * t + 1) {
            const float* A = abuf[cur];
            float4 a  = *(const float4*)(A + 16 + 4 * i);
            float hm  = A[15 + 4 * i];
            int Ei = gexp[cur][i];
            int Em = (i > 0) ? gexp[cur][i - 1] : EMPTYE;
            int Eref = max(Ei, Em);
            float sA = exp2i_neg(Ei - Eref);
            float sH = exp2i_neg(Em - Eref);
            float ax = a.x * sA, ay = a.y * sA, az = a.z * sA, aw = a.w * sA;
            float h  = hm * sH;
            float ptb, pt0, pt1;
            if (st < 4) {
                ptb = f4c(pshA[pb][1],      st);
                pt0 = f4c(pshA[pb][lbl[8]], st);
                pt1 = f4c(pshA[pb][lbl[9]], st);
            } else {
                ptb = f4c(pshB[pb][1],      st - 4);
                pt0 = f4c(pshB[pb][lbl[8]], st - 4);
                pt1 = f4c(pshB[pb][lbl[9]], st - 4);
            }
            float cs0 = csv[8], cs1 = csv[9];
            float n0 = (ax + h) * ptb * m0;
            float n1 = (ay + fmaf(cs0, h, ax)) * pt0 * m1;
            float n2 = (az + ay) * ptb * m2;
            float n3 = (aw + fmaf(cs1, ay, az)) * pt1 * m3;
            float gm = fmaxf(fmaxf(n0, n1), fmaxf(n2, n3));
            int newE; float sc;
            if (gm > 0.f) {
                int e = ((__float_as_int(gm) >> 23) & 255) - 127;
                newE = Eref + e;
                sc = __int_as_float((127 - e) << 23);
            } else {
                newE = EMPTYE;
                sc = 0.f;
            }
            *(float4*)(abuf[cur ^ 1] + 16 + 4 * i) =
                make_float4(n0 * sc, n1 * sc, n2 * sc, n3 * sc);
            gexp[cur ^ 1][i] = newE;
        }
        __syncthreads();
        cur ^= 1;
    }

    if (tid == 0) {
        const int send = 2 * tl;
        float v1 = abuf[cur][16 + send];      // alpha[2*tl]
        float v0 = abuf[cur][15 + send];      // alpha[2*tl - 1]
        int E1 = gexp[cur][send >> 2];
        int E0 = gexp[cur][(send - 1) >> 2];
        int M = EMPTYE;
        if (v1 > 0.f) M = max(M, E1);
        if (v0 > 0.f) M = max(M, E0);
        float outv = 0.f;
        if (M != EMPTYE) {
            double s = 0.0;
            if (v1 > 0.f) s += ldexp((double)v1, E1 - M);
            if (v0 > 0.f) s += ldexp((double)v0, E0 - M);
            double ll = log(s) + (double)M * 0.6931471805599453;
            double l = -ll;
            if (!(l < 1e29)) l = 0.0;
            outv = (float)(l / (double)tl);
        }
        g_partial[b] = outv;
    }
}

__global__ void ctc_reduce(float* __restrict__ out, int B)
{
    int tid = threadIdx.x;
    float v = 0.f;
    for (int j = tid; j < B; j += 32) v += g_partial[j];
    #pragma unroll
    for (int o = 16; o; o >>= 1) v += __shfl_xor_sync(0xffffffffu, v, o);
    if (tid == 0) out[0] = v / (float)B;
}

extern "C" void kernel_launch(void* const* d_in, const int* in_sizes, int n_in,
                              void* d_out, int out_size)
{
    const float* logp    = (const float*)d_in[0];
    const int*   targets = (const int*)d_in[1];
    const int*   il      = (const int*)d_in[2];
    const int*   tl      = (const int*)d_in[3];
    const int B = in_sizes[2];
    const int S = in_sizes[1] / B;
    const int T = in_sizes[0] / (B * VOCAB);

    ctc_scan<<<B, NT>>>(logp, targets, il, tl, T, S);
    ctc_reduce<<<1, 32>>>((float*)d_out, B);
}

// round 13
// speedup vs baseline: 1.5540x; 1.5540x over previous
#include <cuda_runtime.h>
#include <cuda_bf16.h>
#include <math.h>

#define NT     128
#define VOCAB  256
#define EMPTYE (-(1 << 28))   // exponent sentinel for "group has no mass"

// per-batch partial losses (loss_b / tl_b)
__device__ float g_partial[1024];

// 2^d for d <= 0 (flushes to 0 below -126). d==0 -> 1.0f.
__device__ __forceinline__ float exp2i_neg(int d) {
    return (d < -126) ? 0.f : __int_as_float((127 + d) << 23);
}

// Constant-index float4 component access (folds under full unroll).
__device__ __forceinline__ float f4c(float4 v, int c) {
    switch (c & 3) {
        case 0:  return v.x;
        case 1:  return v.y;
        case 2:  return v.z;
        default: return v.w;
    }
}

// One CTA per batch element, 128 threads, EIGHT states per thread.
// Linear-domain CTC forward scan, per-group (8-state) block-floating-point
// exponents, EIGHT time steps fused per barrier (16-state halo pyramid in
// registers -> only 1.875x redundancy), time-transposed probability staging.
__global__ __launch_bounds__(NT, 1) void ctc_scan(
    const float* __restrict__ logp,      // [B, T, VOCAB]
    const int*   __restrict__ targets,   // [B, S]
    const int*   __restrict__ input_len, // [B]
    const int*   __restrict__ target_len,// [B]
    int T, int S)
{
    const int b   = blockIdx.x;
    const int tid = threadIdx.x;
    const float* lp = logp    + (size_t)b * T * VOCAB;
    const int*   tg = targets + (size_t)b * S;
    const int il = input_len[b];
    const int tl = target_len[b];
    const int Lb = 2 * tl + 1;               // number of valid extended states
    const int ng = (Lb + 7) >> 3;            // groups of 8 states

    // alpha mantissas at abuf[buf][16 + s]; [0..15] zero padding for the halo.
    __shared__ float  abuf[2][824];
    __shared__ int    gexp[2][104];          // per-group exponents
    __shared__ float4 pshA[2][VOCAB];        // [buf][v] = exp(logp[t..t+3][v])
    __shared__ float4 pshB[2][VOCAB];        // [buf][v] = exp(logp[t+4..t+7][v])

    for (int j = tid; j < 824; j += NT) { abuf[0][j] = 0.f; abuf[1][j] = 0.f; }
    for (int j = tid; j < 104; j += NT) { gexp[0][j] = EMPTYE; gexp[1][j] = EMPTYE; }
    __syncthreads();

    // Thread i owns states 8i..8i+7; pyramid spans states 8i-16..8i+7 (k=0..23).
    // Odd k=2m+1 -> state 8i-16+k has label tg[4i-8+m], m=0..11.
    const int i = tid;
    int   lbl[12];
    float csv[12];
    float msk[8];
    const bool isg = (i < ng);
    #pragma unroll
    for (int m = 0; m < 12; ++m) {
        int j = 4 * i - 8 + m;
        int lj  = (j >= 0 && j < S) ? tg[j] : 0;
        int ljm = (j - 1 >= 0 && j - 1 < S) ? tg[j - 1] : -1;
        lbl[m] = lj;
        csv[m] = (j >= 1 && lj != ljm) ? 1.f : 0.f;
    }
    #pragma unroll
    for (int k = 0; k < 8; ++k)
        msk[k] = (isg && 8 * i + k < Lb) ? 1.f : 0.f;

    // Two vocab entries per thread: v0 = tid, v1 = tid + 128.
    #define RAWV(r, v) (((r) < T) ? lp[(size_t)(r) * VOCAB + (v)] : 0.f)
    #define EXPV(r, v) (((r) < T) ? __expf(lp[(size_t)(r) * VOCAB + (v)]) : 0.f)
    const int v0 = tid, v1 = tid + NT;
    // Prologue: stage exp rows 1..8; raw queue = rows 9..16 (both vocab halves).
    pshA[0][v0] = make_float4(EXPV(1, v0), EXPV(2, v0), EXPV(3, v0), EXPV(4, v0));
    pshA[0][v1] = make_float4(EXPV(1, v1), EXPV(2, v1), EXPV(3, v1), EXPV(4, v1));
    pshB[0][v0] = make_float4(EXPV(5, v0), EXPV(6, v0), EXPV(7, v0), EXPV(8, v0));
    pshB[0][v1] = make_float4(EXPV(5, v1), EXPV(6, v1), EXPV(7, v1), EXPV(8, v1));
    float qa0 = RAWV(9,  v0), qa1 = RAWV(10, v0), qa2 = RAWV(11, v0), qa3 = RAWV(12, v0);
    float qa4 = RAWV(13, v0), qa5 = RAWV(14, v0), qa6 = RAWV(15, v0), qa7 = RAWV(16, v0);
    float qb0 = RAWV(9,  v1), qb1 = RAWV(10, v1), qb2 = RAWV(11, v1), qb3 = RAWV(12, v1);
    float qb4 = RAWV(13, v1), qb5 = RAWV(14, v1), qb6 = RAWV(15, v1), qb7 = RAWV(16, v1);
    // alpha_0: states 0 (blank) and 1 (first target); group 0 exponent = 0.
    if (tid == 0) { abuf[0][16] = __expf(lp[1]); gexp[0][0] = 0; }
    if (tid == 1) { abuf[0][17] = __expf(lp[tg[0]]); }
    __syncthreads();

    int cur = 0, pb = 0;
    int t = 1;

    // Fused loop: each iteration advances steps t..t+7 with ONE barrier.
    for (; t + 7 < il; t += 8) {
        // Stage exp rows t+8..t+15; refill queue with rows t+16..t+23.
        pshA[pb ^ 1][v0] = make_float4(__expf(qa0), __expf(qa1), __expf(qa2), __expf(qa3));
        pshA[pb ^ 1][v1] = make_float4(__expf(qb0), __expf(qb1), __expf(qb2), __expf(qb3));
        pshB[pb ^ 1][v0] = make_float4(__expf(qa4), __expf(qa5), __expf(qa6), __expf(qa7));
        pshB[pb ^ 1][v1] = make_float4(__expf(qb4), __expf(qb5), __expf(qb6), __expf(qb7));
        qa0 = RAWV(t + 16, v0); qa1 = RAWV(t + 17, v0); qa2 = RAWV(t + 18, v0); qa3 = RAWV(t + 19, v0);
        qa4 = RAWV(t + 20, v0); qa5 = RAWV(t + 21, v0); qa6 = RAWV(t + 22, v0); qa7 = RAWV(t + 23, v0);
        qb0 = RAWV(t + 16, v1); qb1 = RAWV(t + 17, v1); qb2 = RAWV(t + 18, v1); qb3 = RAWV(t + 19, v1);
        qb4 = RAWV(t + 20, v1); qb5 = RAWV(t + 21, v1); qb6 = RAWV(t + 22, v1); qb7 = RAWV(t + 23, v1);

        // Own states reachable at step t+7 iff 8i <= 2(t+7)+1.
        if (isg && 8 * i <= 2 * t + 15) {
            const float* A = abuf[cur];
            // k=0..23 -> abuf index 16 + (8i-16) + k = 8i + k.
            float4 g0 = *(const float4*)(A + 8 * i);        // k 0..3
            float4 g1 = *(const float4*)(A + 8 * i + 4);    // k 4..7
            float4 g2 = *(const float4*)(A + 8 * i + 8);    // k 8..11
            float4 g3 = *(const float4*)(A + 8 * i + 12);   // k 12..15
            float4 g4 = *(const float4*)(A + 8 * i + 16);   // k 16..19 (own)
            float4 g5 = *(const float4*)(A + 8 * i + 20);   // k 20..23 (own)
            int E0 = (i > 1) ? gexp[cur][i - 2] : EMPTYE;
            int E1 = (i > 0) ? gexp[cur][i - 1] : EMPTYE;
            int E2 = gexp[cur][i];
            int Eref = max(max(E0, E1), E2);
            float s0 = exp2i_neg(E0 - Eref);
            float s1 = exp2i_neg(E1 - Eref);
            float s2 = exp2i_neg(E2 - Eref);

            float xs[24];
            xs[0]=g0.x*s0;  xs[1]=g0.y*s0;  xs[2]=g0.z*s0;  xs[3]=g0.w*s0;
            xs[4]=g1.x*s0;  xs[5]=g1.y*s0;  xs[6]=g1.z*s0;  xs[7]=g1.w*s0;
            xs[8]=g2.x*s1;  xs[9]=g2.y*s1;  xs[10]=g2.z*s1; xs[11]=g2.w*s1;
            xs[12]=g3.x*s1; xs[13]=g3.y*s1; xs[14]=g3.z*s1; xs[15]=g3.w*s1;
            xs[16]=g4.x*s2; xs[17]=g4.y*s2; xs[18]=g4.z*s2; xs[19]=g4.w*s2;
            xs[20]=g5.x*s2; xs[21]=g5.y*s2; xs[22]=g5.z*s2; xs[23]=g5.w*s2;

            const float4* PA = pshA[pb];
            const float4* PB = pshB[pb];
            float4 Pv[12];
            float4 BK = PA[1];
            #pragma unroll
            for (int m = 0; m < 12; ++m) Pv[m] = PA[lbl[m]];

            // Layers 1..4 (rows t..t+3): compute k = 2j..23 descending (in-place).
            #pragma unroll
            for (int j = 1; j <= 4; ++j) {
                float pbj = f4c(BK, j - 1);
                #pragma unroll
                for (int k = 23; k >= 2 * j; --k) {
                    if ((k & 1) == 0) {
                        xs[k] = (xs[k] + xs[k - 1]) * pbj;
                    } else {
                        const int m = (k - 1) >> 1;
                        float pl = f4c(Pv[m], j - 1);
                        xs[k] = (xs[k] + fmaf(csv[m], xs[k - 2], xs[k - 1])) * pl;
                    }
                }
            }
            // Layers 5..8 (rows t+4..t+7): only labels m>=5 are touched (k>=10).
            BK = PB[1];
            #pragma unroll
            for (int m = 5; m < 12; ++m) Pv[m] = PB[lbl[m]];
            #pragma unroll
            for (int j = 5; j <= 8; ++j) {
                float pbj = f4c(BK, j - 5);
                #pragma unroll
                for (int k = 23; k >= 2 * j; --k) {
                    if ((k & 1) == 0) {
                        xs[k] = (xs[k] + xs[k - 1]) * pbj;
                    } else {
                        const int m = (k - 1) >> 1;
                        float pl = f4c(Pv[m], j - 5);
                        xs[k] = (xs[k] + fmaf(csv[m], xs[k - 2], xs[k - 1])) * pl;
                    }
                }
            }

            // Mask own 8 outputs, renormalize group, store.
            float n0 = xs[16]*msk[0], n1 = xs[17]*msk[1], n2 = xs[18]*msk[2], n3 = xs[19]*msk[3];
            float n4 = xs[20]*msk[4], n5 = xs[21]*msk[5], n6 = xs[22]*msk[6], n7 = xs[23]*msk[7];
            float gm = fmaxf(fmaxf(fmaxf(n0, n1), fmaxf(n2, n3)),
                             fmaxf(fmaxf(n4, n5), fmaxf(n6, n7)));
            int newE; float sc;
            if (gm > 0.f) {
                int e = ((__float_as_int(gm) >> 23) & 255) - 127;
                newE = Eref + e;
                sc = __int_as_float((127 - e) << 23);   // 2^-e
            } else {
                newE = EMPTYE;
                sc = 0.f;
            }
            *(float4*)(abuf[cur ^ 1] + 16 + 8 * i) =
                make_float4(n0 * sc, n1 * sc, n2 * sc, n3 * sc);
            *(float4*)(abuf[cur ^ 1] + 20 + 8 * i) =
                make_float4(n4 * sc, n5 * sc, n6 * sc, n7 * sc);
            gexp[cur ^ 1][i] = newE;
        }

        __syncthreads();
        cur ^= 1;
        pb ^= 1;
    }

    // Single-step tail (up to 7 steps). Row t+st: component st of pshA (st<4)
    // or component st-4 of pshB.
    int st = 0;
    for (; t < il; ++t, ++st) {
        if (isg && 8 * i <= 2 * t + 1) {
            const float* A = abuf[cur];
            float4 a0 = *(const float4*)(A + 16 + 8 * i);   // states 8i..8i+3
            float4 a1 = *(const float4*)(A + 20 + 8 * i);   // states 8i+4..8i+7
            float hm  = A[15 + 8 * i];                      // state 8i-1
            int Ei = gexp[cur][i];
            int Em = (i > 0) ? gexp[cur][i - 1] : EMPTYE;
            int Eref = max(Ei, Em);
            float sA = exp2i_neg(Ei - Eref);
            float sH = exp2i_neg(Em - Eref);
            float x0 = a0.x*sA, x1 = a0.y*sA, x2 = a0.z*sA, x3 = a0.w*sA;
            float x4 = a1.x*sA, x5 = a1.y*sA, x6 = a1.z*sA, x7 = a1.w*sA;
            float h  = hm * sH;
            float ptb, pl0, pl1, pl2, pl3;
            if (st < 4) {
                const float4* PA = pshA[pb];
                ptb = f4c(PA[1], st);
                pl0 = f4c(PA[lbl[8]],  st); pl1 = f4c(PA[lbl[9]],  st);
                pl2 = f4c(PA[lbl[10]], st); pl3 = f4c(PA[lbl[11]], st);
            } else {
                const float4* PB = pshB[pb];
                ptb = f4c(PB[1], st - 4);
                pl0 = f4c(PB[lbl[8]],  st - 4); pl1 = f4c(PB[lbl[9]],  st - 4);
                pl2 = f4c(PB[lbl[10]], st - 4); pl3 = f4c(PB[lbl[11]], st - 4);
            }
            float n0 = (x0 + h) * ptb * msk[0];
            float n1 = (x1 + fmaf(csv[8],  h,  x0)) * pl0 * msk[1];
            float n2 = (x2 + x1) * ptb * msk[2];
            float n3 = (x3 + fmaf(csv[9],  x1, x2)) * pl1 * msk[3];
            float n4 = (x4 + x3) * ptb * msk[4];
            float n5 = (x5 + fmaf(csv[10], x3, x4)) * pl2 * msk[5];
            float n6 = (x6 + x5) * ptb * msk[6];
            float n7 = (x7 + fmaf(csv[11], x5, x6)) * pl3 * msk[7];
            float gm = fmaxf(fmaxf(fmaxf(n0, n1), fmaxf(n2, n3)),
                             fmaxf(fmaxf(n4, n5), fmaxf(n6, n7)));
            int newE; float sc;
            if (gm > 0.f) {
                int e = ((__float_as_int(gm) >> 23) & 255) - 127;
                newE = Eref + e;
                sc = __int_as_float((127 - e) << 23);
            } else {
                newE = EMPTYE;
                sc = 0.f;
            }
            *(float4*)(abuf[cur ^ 1] + 16 + 8 * i) =
                make_float4(n0 * sc, n1 * sc, n2 * sc, n3 * sc);
            *(float4*)(abuf[cur ^ 1] + 20 + 8 * i) =
                make_float4(n4 * sc, n5 * sc, n6 * sc, n7 * sc);
            gexp[cur ^ 1][i] = newE;
        }
        __syncthreads();
        cur ^= 1;
    }

    if (tid == 0) {
        const int send = 2 * tl;
        float v1 = abuf[cur][16 + send];      // alpha[2*tl]
        float v0 = abuf[cur][15 + send];      // alpha[2*tl - 1]
        int E1 = gexp[cur][send >> 3];
        int E0 = gexp[cur][(send - 1) >> 3];
        int M = EMPTYE;
        if (v1 > 0.f) M = max(M, E1);
        if (v0 > 0.f) M = max(M, E0);
        float outv = 0.f;
        if (M != EMPTYE) {
            double s = 0.0;
            if (v1 > 0.f) s += ldexp((double)v1, E1 - M);
            if (v0 > 0.f) s += ldexp((double)v0, E0 - M);
            double ll = log(s) + (double)M * 0.6931471805599453;
            double l = -ll;
            if (!(l < 1e29)) l = 0.0;
            outv = (float)(l / (double)tl);
        }
        g_partial[b] = outv;
    }
}

__global__ void ctc_reduce(float* __restrict__ out, int B)
{
    int tid = threadIdx.x;
    float v = 0.f;
    for (int j = tid; j < B; j += 32) v += g_partial[j];
    #pragma unroll
    for (int o = 16; o; o >>= 1) v += __shfl_xor_sync(0xffffffffu, v, o);
    if (tid == 0) out[0] = v / (float)B;
}

extern "C" void kernel_launch(void* const* d_in, const int* in_sizes, int n_in,
                              void* d_out, int out_size)
{
    const float* logp    = (const float*)d_in[0];
    const int*   targets = (const int*)d_in[1];
    const int*   il      = (const int*)d_in[2];
    const int*   tl      = (const int*)d_in[3];
    const int B = in_sizes[2];
    const int S = in_sizes[1] / B;
    const int T = in_sizes[0] / (B * VOCAB);

    ctc_scan<<<B, NT>>>(logp, targets, il, tl, T, S);
    ctc_reduce<<<1, 32>>>((float*)d_out, B);
}